// round 10
// baseline (speedup 1.0000x reference)
#include <cuda_runtime.h>
#include <cuda_bf16.h>
#include <mma.h>
#include <cstdint>

using namespace nvcuda;

// Fixed shapes
#define B_      2
#define L_      512
#define D_      256
#define KHALF   128                       // K per CTA (split across 2 CTAs)
#define TILE    64
#define THREADS 512
#define SSTK    136                       // 128 + 8 pad bf16 (272B rows)
#define TEL     (TILE * SSTK)             // elems per operand matrix
#define SMEM_BYTES (4 * TEL * 2)          // 69632 B
#define PST     68                        // partial stride (floats, 272B rows)
#define NPAIR   36                        // ti<=tj tile pairs per batch

// out[b,i,j] = sum_d x[b,i,d]*w1[d]*x[b,j,d] + bias   (symmetric in i,j)
// (lin_i - lin_j cancels under (P+P^T)/2; w2 dead.)
// split-bf16 3-product: a*x ≈ ahi*xhi + ahi*xlo + alo*xhi (rel ~2^-18)

// Cross-CTA scratch: partial tiles + flags (one per (batch,pair))
__device__ float gPart[B_ * NPAIR * TILE * TILE];
__device__ volatile int gFlag[B_ * NPAIR];   // zero-init at load; self-resetting

__device__ __forceinline__ uint32_t cvt2(float a, float b) {
    __nv_bfloat162 h = __floats2bfloat162_rn(a, b);
    return *reinterpret_cast<uint32_t*>(&h);
}
__device__ __forceinline__ void split4(const float* v, uint2& hi, uint2& lo) {
    uint32_t h01 = cvt2(v[0], v[1]);
    uint32_t h23 = cvt2(v[2], v[3]);
    float f0 = __uint_as_float(h01 << 16);
    float f1 = __uint_as_float(h01 & 0xFFFF0000u);
    float f2 = __uint_as_float(h23 << 16);
    float f3 = __uint_as_float(h23 & 0xFFFF0000u);
    hi.x = h01; hi.y = h23;
    lo.x = cvt2(v[0] - f0, v[1] - f1);
    lo.y = cvt2(v[2] - f2, v[3] - f3);
}

__global__ __launch_bounds__(THREADS, 1)
void fused_pairwise_kernel(const float* __restrict__ x,
                           const float* __restrict__ W,
                           const float* __restrict__ bias_p,
                           float* __restrict__ out) {
    extern __shared__ __align__(16) __nv_bfloat16 smem[];
    __nv_bfloat16* sAhi = smem;
    __nv_bfloat16* sAlo = smem + TEL;
    __nv_bfloat16* sBhi = smem + 2 * TEL;
    __nv_bfloat16* sBlo = smem + 3 * TEL;
    float* P0 = (float*)smem;             // reused after MMA: ks=0 partial / final
    float* P1 = P0 + TILE * PST;          // ks=1 partial

    const int pairix = blockIdx.x;        // 0..35
    const int bz     = blockIdx.y;        // batch
    const int kh     = blockIdx.z;        // K half (0 combines, 1 produces)
    const int tid  = threadIdx.x;
    const int warp = tid >> 5;

    // triangular pair -> (ti, tj), ti <= tj
    int p = pairix, ti = 0, rowlen = 8;
    while (p >= rowlen) { p -= rowlen; rowlen--; ti++; }
    const int tj = ti + p;
    const int pp = bz * NPAIR + pairix;

    // ---- front end: load K-half, convert, STS ----
    const float4* A4 = (const float4*)(x + (size_t)(bz * L_ + ti * TILE) * D_);
    const float4* B4 = (const float4*)(x + (size_t)(bz * L_ + tj * TILE) * D_);
    const float4* W4 = (const float4*)W;

    float4 ra[4], rb[4];
    #pragma unroll
    for (int i = 0; i < 4; i++) {
        int lin = i * THREADS + tid;       // 0..2047
        int row = lin >> 5;                // 0..63
        int c4  = lin & 31;                // float4 within K-half
        ra[i] = A4[row * 64 + kh * 32 + c4];
        rb[i] = B4[row * 64 + kh * 32 + c4];
    }
    #pragma unroll
    for (int i = 0; i < 4; i++) {
        int lin = i * THREADS + tid;
        int row = lin >> 5;
        int c4  = lin & 31;
        float4 wv = __ldg(&W4[kh * 32 + c4]);
        float av[4] = {ra[i].x * wv.x, ra[i].y * wv.y,
                       ra[i].z * wv.z, ra[i].w * wv.w};
        float bv[4] = {rb[i].x, rb[i].y, rb[i].z, rb[i].w};
        uint2 ahi, alo, bhi, blo;
        split4(av, ahi, alo);
        split4(bv, bhi, blo);
        int off = row * SSTK + c4 * 4;
        *(uint2*)&sAhi[off] = ahi;
        *(uint2*)&sAlo[off] = alo;
        *(uint2*)&sBhi[off] = bhi;
        *(uint2*)&sBlo[off] = blo;
    }
    __syncthreads();

    // ---- MMA: 8 warps = 2x2 spatial x 2 k-sub-halves, 32x32 per warp ----
    wmma::fragment<wmma::accumulator, 16, 16, 16, float> acc[2][2];
    const int wr = (warp >> 1) & 1;
    const int wc = warp & 1;
    const int ks = warp >> 2;             // sub-half of this CTA's K=128

    if (warp < 8) {
        #pragma unroll
        for (int r = 0; r < 2; r++)
            #pragma unroll
            for (int c = 0; c < 2; c++)
                wmma::fill_fragment(acc[r][c], 0.0f);

        const int kb = ks * 64;
        const __nv_bfloat16* Ah = sAhi + (wr * 32) * SSTK + kb;
        const __nv_bfloat16* Al = sAlo + (wr * 32) * SSTK + kb;
        const __nv_bfloat16* Bh = sBhi + (wc * 32) * SSTK + kb;
        const __nv_bfloat16* Bl = sBlo + (wc * 32) * SSTK + kb;

        #pragma unroll
        for (int kk = 0; kk < 64; kk += 16) {
            wmma::fragment<wmma::matrix_a, 16, 16, 16, __nv_bfloat16, wmma::row_major> ah[2], al[2];
            wmma::fragment<wmma::matrix_b, 16, 16, 16, __nv_bfloat16, wmma::col_major> bh[2], bl[2];
            #pragma unroll
            for (int r = 0; r < 2; r++) {
                wmma::load_matrix_sync(ah[r], Ah + r * 16 * SSTK + kk, SSTK);
                wmma::load_matrix_sync(al[r], Al + r * 16 * SSTK + kk, SSTK);
            }
            #pragma unroll
            for (int c = 0; c < 2; c++) {
                wmma::load_matrix_sync(bh[c], Bh + c * 16 * SSTK + kk, SSTK);
                wmma::load_matrix_sync(bl[c], Bl + c * 16 * SSTK + kk, SSTK);
            }
            #pragma unroll
            for (int r = 0; r < 2; r++) {
                #pragma unroll
                for (int c = 0; c < 2; c++) {
                    wmma::mma_sync(acc[r][c], ah[r], bh[c], acc[r][c]);
                    wmma::mma_sync(acc[r][c], ah[r], bl[c], acc[r][c]);
                    wmma::mma_sync(acc[r][c], al[r], bh[c], acc[r][c]);
                }
            }
        }
    }
    __syncthreads();   // operand smem dead; becomes partial buffers

    if (warp < 8) {
        float* P = ks ? P1 : P0;
        #pragma unroll
        for (int r = 0; r < 2; r++)
            #pragma unroll
            for (int c = 0; c < 2; c++)
                wmma::store_matrix_sync(P + (wr * 32 + r * 16) * PST + wc * 32 + c * 16,
                                        acc[r][c], PST, wmma::mem_row_major);
    }
    __syncthreads();

    // per-thread own sum over the 2 k-sub-halves: 2 float4 chunks
    float4 own[2];
    int rown[2], ccol[2];
    #pragma unroll
    for (int i = 0; i < 2; i++) {
        int lin = i * THREADS + tid;       // 0..1023 float4 units
        rown[i] = lin >> 4;                // 0..63
        ccol[i] = (lin & 15) * 4;          // float col 0..60
        float4 v0 = *(float4*)&P0[rown[i] * PST + ccol[i]];
        float4 v1 = *(float4*)&P1[rown[i] * PST + ccol[i]];
        own[i].x = v0.x + v1.x;  own[i].y = v0.y + v1.y;
        own[i].z = v0.z + v1.z;  own[i].w = v0.w + v1.w;
    }

    float* part = gPart + (size_t)pp * TILE * TILE;

    if (kh == 1) {
        // producer: publish partial, set flag
        #pragma unroll
        for (int i = 0; i < 2; i++)
            *(float4*)&part[rown[i] * TILE + ccol[i]] = own[i];
        __threadfence();
        __syncthreads();
        if (tid == 0) gFlag[pp] = 1;
        return;
    }

    // ---- combiner (kh == 0) ----
    if (tid == 0) {
        while (gFlag[pp] == 0) { }
        gFlag[pp] = 0;                     // reset for next replay
        __threadfence();
    }
    __syncthreads();

    const float bias = bias_p[0];
    float* ob = out + (size_t)bz * L_ * L_ + (size_t)(ti * TILE) * L_ + tj * TILE;
    float4 fin[2];
    #pragma unroll
    for (int i = 0; i < 2; i++) {
        float4 pv = *(float4*)&part[rown[i] * TILE + ccol[i]];
        fin[i].x = own[i].x + pv.x + bias;
        fin[i].y = own[i].y + pv.y + bias;
        fin[i].z = own[i].z + pv.z + bias;
        fin[i].w = own[i].w + pv.w + bias;
        *(float4*)(ob + (size_t)rown[i] * L_ + ccol[i]) = fin[i];
    }

    if (ti != tj) {
        __syncthreads();                   // P0/P1 reads above done
        #pragma unroll
        for (int i = 0; i < 2; i++)        // stash final for transpose
            *(float4*)&P0[rown[i] * PST + ccol[i]] = fin[i];
        __syncthreads();
        // transposed block at (tj, ti): out_t[r'][c'] = final[c'][r']
        float* obt = out + (size_t)bz * L_ * L_ + (size_t)(tj * TILE) * L_ + ti * TILE;
        #pragma unroll
        for (int i = 0; i < 2; i++) {
            int lin = i * THREADS + tid;
            int rp  = lin >> 4;            // r' 0..63
            int cp  = (lin & 15) * 4;      // c' base
            float4 v;
            v.x = P0[(cp + 0) * PST + rp];
            v.y = P0[(cp + 1) * PST + rp];
            v.z = P0[(cp + 2) * PST + rp];
            v.w = P0[(cp + 3) * PST + rp];
            *(float4*)(obt + (size_t)rp * L_ + cp) = v;
        }
    }
}

// ---------------------------------------------------------------------------
// d_in[0] = inputs f32 (2,512,256), d_in[1] = W f32 (512,1), d_in[2] = b f32 (1,)
// d_out   = f32 (2,512,512,1)
// ---------------------------------------------------------------------------
extern "C" void kernel_launch(void* const* d_in, const int* in_sizes, int n_in,
                              void* d_out, int out_size) {
    const float* x    = (const float*)d_in[0];
    const float* W    = (const float*)d_in[1];
    const float* bptr = (const float*)d_in[2];
    float* out = (float*)d_out;

    static bool attr_set = false;
    if (!attr_set) {
        cudaFuncSetAttribute(fused_pairwise_kernel,
                             cudaFuncAttributeMaxDynamicSharedMemorySize, SMEM_BYTES);
        attr_set = true;
    }

    // (36 pairs, 2 batches, 2 K-halves) = 144 CTAs, 1/SM, single wave on 148 SMs
    dim3 grid(NPAIR, B_, 2);
    fused_pairwise_kernel<<<grid, THREADS, SMEM_BYTES>>>(x, W, bptr, out);
}

// round 11
// speedup vs baseline: 1.5055x; 1.5055x over previous
#include <cuda_runtime.h>
#include <cuda_fp16.h>
#include <mma.h>
#include <cstdint>

using namespace nvcuda;

// Fixed shapes
#define B_      2
#define L_      512
#define D_      256
#define TILE    64
#define THREADS 512
#define SST     264                      // 256 + 8 pad (fp16 elems; 528B rows)
#define TEL     (TILE * SST)
#define SMEM_BYTES (2 * TEL * 2)         // 67584 B (A and B fp16 tiles)

// out[b,i,j] = sum_d x[b,i,d]*w1[d]*x[b,j,d] + bias   (symmetric)
// (lin_i - lin_j cancels under (P+P^T)/2 symmetrization; w2 = W[D:,0] dead.)
//
// Precision: single-product fp16: fp16(x*w1) . fp16(x)^T with f32 accumulate.
// Per-element rounding (half-ulp 2^-11) is zero-mean across K=256 ->
// norm-based rel err ~ 0.82 * 2^-11 ~ 4e-4 < 1e-3 threshold.

__device__ __forceinline__ uint32_t h2(float a, float b) {
    __half2 h = __floats2half2_rn(a, b);
    return *reinterpret_cast<uint32_t*>(&h);
}

__global__ __launch_bounds__(THREADS, 1)
void fused_pairwise_kernel(const float* __restrict__ x,
                           const float* __restrict__ W,
                           const float* __restrict__ bias_p,
                           float* __restrict__ out) {
    extern __shared__ __align__(16) __half smem[];
    __half* sA = smem;            // fp16(x*w1), rows = i-tile
    __half* sB = smem + TEL;      // fp16(x),    rows = j-tile

    const int bz  = blockIdx.z;
    const int ti  = blockIdx.y;
    const int tj  = blockIdx.x;
    const int tid = threadIdx.x;
    const int warp = tid >> 5;

    const float4* A4 = (const float4*)(x + (size_t)(bz * L_ + ti * TILE) * D_);
    const float4* B4 = (const float4*)(x + (size_t)(bz * L_ + tj * TILE) * D_);
    const float4* W4 = (const float4*)W;   // W[:256] = w1

    // ---- stage gmem: 8 float4 per matrix per thread (MLP 16) ----
    float4 ra[8], rb[8];
    #pragma unroll
    for (int i = 0; i < 8; i++) {
        int lin = i * THREADS + tid;       // 0..4095
        int row = lin >> 6;                // 0..63
        int c4  = lin & 63;
        ra[i] = A4[row * 64 + c4];
        rb[i] = B4[row * 64 + c4];
    }

    // ---- fp16 convert + STS ----
    #pragma unroll
    for (int i = 0; i < 8; i++) {
        int lin = i * THREADS + tid;
        int row = lin >> 6;
        int c4  = lin & 63;
        float4 wv = __ldg(&W4[c4]);

        uint2 av, bv;
        av.x = h2(ra[i].x * wv.x, ra[i].y * wv.y);
        av.y = h2(ra[i].z * wv.z, ra[i].w * wv.w);
        bv.x = h2(rb[i].x, rb[i].y);
        bv.y = h2(rb[i].z, rb[i].w);

        int off = row * SST + c4 * 4;      // 8B-aligned
        *(uint2*)&sA[off] = av;
        *(uint2*)&sB[off] = bv;
    }
    __syncthreads();

    // ---- MMA: warps 0-3, 2x2 layout, 32x32 per warp, full K=256 ----
    if (warp >= 4) return;

    const int wr = (warp >> 1) & 1;
    const int wc = warp & 1;

    wmma::fragment<wmma::accumulator, 16, 16, 16, float> acc[2][2];
    #pragma unroll
    for (int r = 0; r < 2; r++)
        #pragma unroll
        for (int c = 0; c < 2; c++)
            wmma::fill_fragment(acc[r][c], 0.0f);

    const __half* Ab = sA + (wr * 32) * SST;
    const __half* Bb = sB + (wc * 32) * SST;

    #pragma unroll
    for (int kk = 0; kk < D_; kk += 16) {
        wmma::fragment<wmma::matrix_a, 16, 16, 16, __half, wmma::row_major> af[2];
        wmma::fragment<wmma::matrix_b, 16, 16, 16, __half, wmma::col_major> bf[2];
        #pragma unroll
        for (int r = 0; r < 2; r++)
            wmma::load_matrix_sync(af[r], Ab + r * 16 * SST + kk, SST);
        #pragma unroll
        for (int c = 0; c < 2; c++)
            wmma::load_matrix_sync(bf[c], Bb + c * 16 * SST + kk, SST);
        #pragma unroll
        for (int r = 0; r < 2; r++)
            #pragma unroll
            for (int c = 0; c < 2; c++)
                wmma::mma_sync(acc[r][c], af[r], bf[c], acc[r][c]);
    }

    // ---- epilogue: bias + direct store ----
    const float bias = bias_p[0];
    #pragma unroll
    for (int r = 0; r < 2; r++) {
        #pragma unroll
        for (int c = 0; c < 2; c++) {
            #pragma unroll
            for (int t = 0; t < acc[r][c].num_elements; t++)
                acc[r][c].x[t] += bias;
            int gi = ti * TILE + wr * 32 + r * 16;
            int gj = tj * TILE + wc * 32 + c * 16;
            float* dst = out + (size_t)bz * L_ * L_ + (size_t)gi * L_ + gj;
            wmma::store_matrix_sync(dst, acc[r][c], L_, wmma::mem_row_major);
        }
    }
}

// ---------------------------------------------------------------------------
// d_in[0] = inputs f32 (2,512,256), d_in[1] = W f32 (512,1), d_in[2] = b f32 (1,)
// d_out   = f32 (2,512,512,1)
// ---------------------------------------------------------------------------
extern "C" void kernel_launch(void* const* d_in, const int* in_sizes, int n_in,
                              void* d_out, int out_size) {
    const float* x    = (const float*)d_in[0];
    const float* W    = (const float*)d_in[1];
    const float* bptr = (const float*)d_in[2];
    float* out = (float*)d_out;

    static bool attr_set = false;
    if (!attr_set) {
        cudaFuncSetAttribute(fused_pairwise_kernel,
                             cudaFuncAttributeMaxDynamicSharedMemorySize, SMEM_BYTES);
        attr_set = true;
    }

    dim3 grid(L_ / TILE, L_ / TILE, B_);   // (8, 8, 2) = 128 CTAs, single wave
    fused_pairwise_kernel<<<grid, THREADS, SMEM_BYTES>>>(x, W, bptr, out);
}

// round 12
// speedup vs baseline: 1.5111x; 1.0037x over previous
#include <cuda_runtime.h>
#include <cuda_fp16.h>
#include <mma.h>
#include <cstdint>

using namespace nvcuda;

// Fixed shapes
#define B_      2
#define L_      512
#define D_      256
#define TILE    64
#define THREADS 512
#define SST     264                      // fp16 row stride: 256 + 8 pad (528B)
#define TEL     (TILE * SST)
#define SMEM_BYTES (2 * TEL * 2)         // 67584 B

// out[b,i,j] = sum_d x[b,i,d]*w1[d]*x[b,j,d] + bias   (symmetric)
// (lin_i - lin_j cancels under (P+P^T)/2; w2 = W[D:,0] dead.)
// fp16 single product, f32 accumulate: rel err ~3e-4 < 1e-3 (measured R11).

__device__ __forceinline__ uint32_t h2(float a, float b) {
    __half2 h = __floats2half2_rn(a, b);
    return *reinterpret_cast<uint32_t*>(&h);
}

// convert 2 float4 (8 floats) -> 8 fp16 packed in uint4
__device__ __forceinline__ uint4 pack8(float4 f0, float4 f1) {
    uint4 v;
    v.x = h2(f0.x, f0.y);
    v.y = h2(f0.z, f0.w);
    v.z = h2(f1.x, f1.y);
    v.w = h2(f1.z, f1.w);
    return v;
}
__device__ __forceinline__ float4 mul4(float4 a, float4 w) {
    a.x *= w.x; a.y *= w.y; a.z *= w.z; a.w *= w.w;
    return a;
}

__global__ __launch_bounds__(THREADS, 1)
void fused_pairwise_kernel(const float* __restrict__ x,
                           const float* __restrict__ W,
                           const float* __restrict__ bias_p,
                           float* __restrict__ out) {
    extern __shared__ __align__(16) __half smem[];
    __half* sB = smem;            // fp16(x), j-strip rows
    __half* sA = smem + TEL;      // fp16(x*w1), i-strip rows

    const int bz  = blockIdx.z;
    const int ti  = blockIdx.y;
    const int tj  = blockIdx.x;
    const int tid = threadIdx.x;
    const int warp = tid >> 5;

    const float bias = __ldg(bias_p);     // prefetch early; used in epilogue

    const float4* A4 = (const float4*)(x + (size_t)(bz * L_ + ti * TILE) * D_);
    const float4* B4 = (const float4*)(x + (size_t)(bz * L_ + tj * TILE) * D_);
    const float4* W4 = (const float4*)W;  // w1 = W[:256] -> f4 cols 0..63

    // ================= phase A: chunk 0 (f4 cols 0..31), all 512 threads ====
    {
        const int g    = tid >> 8;         // 0 -> B, 1 -> A
        const int u    = tid & 255;
        const int pcol = u & 15;           // pair index (2 f4) within chunk
        const int rblk = u >> 4;           // 0..15 -> rows rblk*4+p
        const int cf4  = pcol * 2;         // f4 col 0..30
        const float4* S = g ? A4 : B4;
        __half* dst = g ? sA : sB;
        float4 w0, w1;
        if (g) { w0 = __ldg(&W4[cf4]); w1 = __ldg(&W4[cf4 + 1]); }

        #pragma unroll
        for (int p = 0; p < 4; p++) {
            int row = rblk * 4 + p;
            float4 f0 = S[row * 64 + cf4];
            float4 f1 = S[row * 64 + cf4 + 1];
            if (g) { f0 = mul4(f0, w0); f1 = mul4(f1, w1); }
            *(uint4*)&dst[row * SST + cf4 * 4] = pack8(f0, f1);
        }
    }
    __syncthreads();

    // ================= phase B: MMA(chunk0) || front-end(chunk1) ============
    wmma::fragment<wmma::accumulator, 16, 16, 16, float> acc[2][2];
    const int wr = (warp >> 1) & 1;
    const int wc = warp & 1;

    if (warp < 4) {
        #pragma unroll
        for (int r = 0; r < 2; r++)
            #pragma unroll
            for (int c = 0; c < 2; c++)
                wmma::fill_fragment(acc[r][c], 0.0f);

        const __half* Ab = sA + (wr * 32) * SST;
        const __half* Bb = sB + (wc * 32) * SST;
        #pragma unroll
        for (int kk = 0; kk < 128; kk += 16) {
            wmma::fragment<wmma::matrix_a, 16, 16, 16, __half, wmma::row_major> af[2];
            wmma::fragment<wmma::matrix_b, 16, 16, 16, __half, wmma::col_major> bf[2];
            #pragma unroll
            for (int r = 0; r < 2; r++)
                wmma::load_matrix_sync(af[r], Ab + r * 16 * SST + kk, SST);
            #pragma unroll
            for (int c = 0; c < 2; c++)
                wmma::load_matrix_sync(bf[c], Bb + c * 16 * SST + kk, SST);
            #pragma unroll
            for (int r = 0; r < 2; r++)
                #pragma unroll
                for (int c = 0; c < 2; c++)
                    wmma::mma_sync(acc[r][c], af[r], bf[c], acc[r][c]);
        }
    } else if (warp >= 8) {
        // chunk 1 (f4 cols 32..63) by warps 8-15 (256 threads)
        const int u    = tid - 256;        // 0..255
        const int g    = u >> 7;           // 0 -> B (warps 8-11), 1 -> A (12-15)
        const int uu   = u & 127;
        const int pcol = uu & 15;
        const int rblk = uu >> 4;          // 0..7 -> rows rblk*8+p
        const int cf4  = 32 + pcol * 2;
        const float4* S = g ? A4 : B4;
        __half* dst = g ? sA : sB;
        float4 w0, w1;
        if (g) { w0 = __ldg(&W4[cf4]); w1 = __ldg(&W4[cf4 + 1]); }

        #pragma unroll
        for (int p = 0; p < 8; p++) {
            int row = rblk * 8 + p;
            float4 f0 = S[row * 64 + cf4];
            float4 f1 = S[row * 64 + cf4 + 1];
            if (g) { f0 = mul4(f0, w0); f1 = mul4(f1, w1); }
            *(uint4*)&dst[row * SST + cf4 * 4] = pack8(f0, f1);
        }
    }
    __syncthreads();

    // ================= phase C: MMA(chunk1) + epilogue (warps 0-3) ==========
    if (warp >= 4) return;

    {
        const __half* Ab = sA + (wr * 32) * SST;
        const __half* Bb = sB + (wc * 32) * SST;
        #pragma unroll
        for (int kk = 128; kk < 256; kk += 16) {
            wmma::fragment<wmma::matrix_a, 16, 16, 16, __half, wmma::row_major> af[2];
            wmma::fragment<wmma::matrix_b, 16, 16, 16, __half, wmma::col_major> bf[2];
            #pragma unroll
            for (int r = 0; r < 2; r++)
                wmma::load_matrix_sync(af[r], Ab + r * 16 * SST + kk, SST);
            #pragma unroll
            for (int c = 0; c < 2; c++)
                wmma::load_matrix_sync(bf[c], Bb + c * 16 * SST + kk, SST);
            #pragma unroll
            for (int r = 0; r < 2; r++)
                #pragma unroll
                for (int c = 0; c < 2; c++)
                    wmma::mma_sync(acc[r][c], af[r], bf[c], acc[r][c]);
        }
    }

    #pragma unroll
    for (int r = 0; r < 2; r++) {
        #pragma unroll
        for (int c = 0; c < 2; c++) {
            #pragma unroll
            for (int t = 0; t < acc[r][c].num_elements; t++)
                acc[r][c].x[t] += bias;
            int gi = ti * TILE + wr * 32 + r * 16;
            int gj = tj * TILE + wc * 32 + c * 16;
            float* dst = out + (size_t)bz * L_ * L_ + (size_t)gi * L_ + gj;
            wmma::store_matrix_sync(dst, acc[r][c], L_, wmma::mem_row_major);
        }
    }
}

// ---------------------------------------------------------------------------
// d_in[0] = inputs f32 (2,512,256), d_in[1] = W f32 (512,1), d_in[2] = b f32 (1,)
// d_out   = f32 (2,512,512,1)
// ---------------------------------------------------------------------------
extern "C" void kernel_launch(void* const* d_in, const int* in_sizes, int n_in,
                              void* d_out, int out_size) {
    const float* x    = (const float*)d_in[0];
    const float* W    = (const float*)d_in[1];
    const float* bptr = (const float*)d_in[2];
    float* out = (float*)d_out;

    static bool attr_set = false;
    if (!attr_set) {
        cudaFuncSetAttribute(fused_pairwise_kernel,
                             cudaFuncAttributeMaxDynamicSharedMemorySize, SMEM_BYTES);
        attr_set = true;
    }

    dim3 grid(L_ / TILE, L_ / TILE, B_);   // (8, 8, 2) = 128 CTAs, single wave
    fused_pairwise_kernel<<<grid, THREADS, SMEM_BYTES>>>(x, W, bptr, out);
}